// round 2
// baseline (speedup 1.0000x reference)
#include <cuda_runtime.h>
#include <cuda_bf16.h>
#include <cstdint>

// Problem constants
#define B_  32
#define T_  4096
#define M_  256     // K dim of GEMM1
#define L_  128     // hidden (cols of GEMM1)

// Tiling
#define PAIRS_PER_CTA 128          // (b,t) pairs per CTA
#define ROWS          256          // 2 * PAIRS_PER_CTA  (h1 rows then h2 rows)
#define KCHUNK        128
#define SSTRIDE       136          // padded bf16 elems per smem row (272B: 4-bank rotation)
#define NTHREADS      256

// smem layout (in bf16 elements)
#define HS_HI_OFF 0
#define HS_LO_OFF (ROWS * SSTRIDE)                       // 34816
#define VS_HI_OFF (2 * ROWS * SSTRIDE)                   // 69632
#define VS_LO_OFF (2 * ROWS * SSTRIDE + L_ * SSTRIDE)    // 87040
#define BF16_TOTAL (2 * ROWS * SSTRIDE + 2 * L_ * SSTRIDE)   // 104448 elems
#define SMEM_BYTES (BF16_TOTAL * 2 + ROWS * 4 + L_ * 4)      // 210432 B

__device__ __forceinline__ float fast_tanh(float x) {
    // tanh(x) = 1 - 2/(e^{2x}+1); __expf/__fdividef err ~2ulp -> ~1e-6 abs
    float e = __expf(2.0f * x);
    return 1.0f - __fdividef(2.0f, e + 1.0f);
}

__device__ __forceinline__ void split2(float a, float b, uint32_t& hi, uint32_t& lo) {
    __nv_bfloat16 ah = __float2bfloat16(a);
    __nv_bfloat16 bh = __float2bfloat16(b);
    __nv_bfloat162 hv; hv.x = ah; hv.y = bh;
    hi = *reinterpret_cast<uint32_t*>(&hv);
    __nv_bfloat162 lv;
    lv.x = __float2bfloat16(a - __bfloat162float(ah));
    lv.y = __float2bfloat16(b - __bfloat162float(bh));
    lo = *reinterpret_cast<uint32_t*>(&lv);
}

__device__ __forceinline__ void mma_bf16(float& c0, float& c1, float& c2, float& c3,
                                         uint32_t a0, uint32_t a1, uint32_t a2, uint32_t a3,
                                         uint32_t b0, uint32_t b1) {
    asm("mma.sync.aligned.m16n8k16.row.col.f32.bf16.bf16.f32 "
        "{%0,%1,%2,%3}, {%4,%5,%6,%7}, {%8,%9}, {%0,%1,%2,%3};\n"
        : "+f"(c0), "+f"(c1), "+f"(c2), "+f"(c3)
        : "r"(a0), "r"(a1), "r"(a2), "r"(a3), "r"(b0), "r"(b1));
}

extern __shared__ char smem_raw[];

__global__ void __launch_bounds__(NTHREADS, 1)
topo_attn_kernel(const float* __restrict__ h1, const float* __restrict__ h2,
                 const float* __restrict__ w_tp, const float* __restrict__ v_tp,
                 float* __restrict__ out)
{
    __nv_bfloat16* sm_bf16 = reinterpret_cast<__nv_bfloat16*>(smem_raw);
    __nv_bfloat16* Hs_hi = sm_bf16 + HS_HI_OFF;
    __nv_bfloat16* Hs_lo = sm_bf16 + HS_LO_OFF;
    __nv_bfloat16* Vs_hi = sm_bf16 + VS_HI_OFF;
    __nv_bfloat16* Vs_lo = sm_bf16 + VS_LO_OFF;
    float* score = reinterpret_cast<float*>(smem_raw + BF16_TOTAL * 2);
    float* ws    = score + ROWS;

    const int tid  = threadIdx.x;
    const int warp = tid >> 5;
    const int lane = tid & 31;
    const int g = lane >> 2;       // group id 0..7
    const int t = lane & 3;        // thread-in-group 0..3
    const int pair0 = blockIdx.x * PAIRS_PER_CTA;
    const int rowBase = warp * 32;

    if (tid < L_) ws[tid] = w_tp[tid];

    float acc[2][16][4];
    #pragma unroll
    for (int s = 0; s < 2; ++s)
        #pragma unroll
        for (int n = 0; n < 16; ++n)
            #pragma unroll
            for (int q = 0; q < 4; ++q)
                acc[s][n][q] = 0.0f;

    for (int kc = 0; kc < M_ / KCHUNK; ++kc) {
        const int k0 = kc * KCHUNK;
        __syncthreads();   // smem chunk buffers free for reuse

        // ---- load + split H chunk: 256 rows x 128 floats; one row per warp-iter (512B coalesced)
        for (int it = 0; it < 32; ++it) {
            int idx = it * NTHREADS + tid;          // float4 index: 256 rows * 32
            int r   = idx >> 5;
            int c4  = idx & 31;
            const float* src = (r < PAIRS_PER_CTA)
                ? (h1 + (size_t)(pair0 + r) * M_)
                : (h2 + (size_t)(pair0 + r - PAIRS_PER_CTA) * M_);
            float4 f = *reinterpret_cast<const float4*>(src + k0 + c4 * 4);
            uint2 hv, lv;
            split2(f.x, f.y, hv.x, lv.x);
            split2(f.z, f.w, hv.y, lv.y);
            *reinterpret_cast<uint2*>(Hs_hi + r * SSTRIDE + c4 * 4) = hv;
            *reinterpret_cast<uint2*>(Hs_lo + r * SSTRIDE + c4 * 4) = lv;
        }
        // ---- load + split V chunk: 128 rows x 128 floats
        for (int it = 0; it < 16; ++it) {
            int idx = it * NTHREADS + tid;
            int r   = idx >> 5;
            int c4  = idx & 31;
            float4 f = *reinterpret_cast<const float4*>(v_tp + (size_t)r * M_ + k0 + c4 * 4);
            uint2 hv, lv;
            split2(f.x, f.y, hv.x, lv.x);
            split2(f.z, f.w, hv.y, lv.y);
            *reinterpret_cast<uint2*>(Vs_hi + r * SSTRIDE + c4 * 4) = hv;
            *reinterpret_cast<uint2*>(Vs_lo + r * SSTRIDE + c4 * 4) = lv;
        }
        __syncthreads();

        // ---- MMA over this K chunk: 8 ksteps of k16
        for (int ks = 0; ks < KCHUNK / 16; ++ks) {
            const int kk = ks * 16;
            uint32_t ahi[2][4], alo[2][4];
            #pragma unroll
            for (int sub = 0; sub < 2; ++sub) {
                const int rb = rowBase + sub * 16;
                const __nv_bfloat16* ph = Hs_hi + kk + 2 * t;
                const __nv_bfloat16* pl = Hs_lo + kk + 2 * t;
                ahi[sub][0] = *reinterpret_cast<const uint32_t*>(ph + (rb + g)     * SSTRIDE);
                ahi[sub][1] = *reinterpret_cast<const uint32_t*>(ph + (rb + g + 8) * SSTRIDE);
                ahi[sub][2] = *reinterpret_cast<const uint32_t*>(ph + (rb + g)     * SSTRIDE + 8);
                ahi[sub][3] = *reinterpret_cast<const uint32_t*>(ph + (rb + g + 8) * SSTRIDE + 8);
                alo[sub][0] = *reinterpret_cast<const uint32_t*>(pl + (rb + g)     * SSTRIDE);
                alo[sub][1] = *reinterpret_cast<const uint32_t*>(pl + (rb + g + 8) * SSTRIDE);
                alo[sub][2] = *reinterpret_cast<const uint32_t*>(pl + (rb + g)     * SSTRIDE + 8);
                alo[sub][3] = *reinterpret_cast<const uint32_t*>(pl + (rb + g + 8) * SSTRIDE + 8);
            }
            #pragma unroll
            for (int nt = 0; nt < 16; ++nt) {
                const int vrow = nt * 8 + g;
                uint32_t bhi0 = *reinterpret_cast<const uint32_t*>(Vs_hi + vrow * SSTRIDE + kk + 2 * t);
                uint32_t bhi1 = *reinterpret_cast<const uint32_t*>(Vs_hi + vrow * SSTRIDE + kk + 2 * t + 8);
                uint32_t blo0 = *reinterpret_cast<const uint32_t*>(Vs_lo + vrow * SSTRIDE + kk + 2 * t);
                uint32_t blo1 = *reinterpret_cast<const uint32_t*>(Vs_lo + vrow * SSTRIDE + kk + 2 * t + 8);
                #pragma unroll
                for (int sub = 0; sub < 2; ++sub) {
                    mma_bf16(acc[sub][nt][0], acc[sub][nt][1], acc[sub][nt][2], acc[sub][nt][3],
                             ahi[sub][0], ahi[sub][1], ahi[sub][2], ahi[sub][3], bhi0, bhi1);
                    mma_bf16(acc[sub][nt][0], acc[sub][nt][1], acc[sub][nt][2], acc[sub][nt][3],
                             ahi[sub][0], ahi[sub][1], ahi[sub][2], ahi[sub][3], blo0, blo1);
                    mma_bf16(acc[sub][nt][0], acc[sub][nt][1], acc[sub][nt][2], acc[sub][nt][3],
                             alo[sub][0], alo[sub][1], alo[sub][2], alo[sub][3], bhi0, bhi1);
                }
            }
        }
    }

    // ---- epilogue: score[row] = sum_l w[l] * tanh(temp[row,l])
    float p00 = 0.f, p01 = 0.f, p10 = 0.f, p11 = 0.f;
    #pragma unroll
    for (int nt = 0; nt < 16; ++nt) {
        float w0 = ws[nt * 8 + 2 * t];
        float w1 = ws[nt * 8 + 2 * t + 1];
        p00 += w0 * fast_tanh(acc[0][nt][0]) + w1 * fast_tanh(acc[0][nt][1]);
        p01 += w0 * fast_tanh(acc[0][nt][2]) + w1 * fast_tanh(acc[0][nt][3]);
        p10 += w0 * fast_tanh(acc[1][nt][0]) + w1 * fast_tanh(acc[1][nt][1]);
        p11 += w0 * fast_tanh(acc[1][nt][2]) + w1 * fast_tanh(acc[1][nt][3]);
    }
    #pragma unroll
    for (int off = 1; off < 4; off <<= 1) {
        p00 += __shfl_xor_sync(0xffffffffu, p00, off);
        p01 += __shfl_xor_sync(0xffffffffu, p01, off);
        p10 += __shfl_xor_sync(0xffffffffu, p10, off);
        p11 += __shfl_xor_sync(0xffffffffu, p11, off);
    }
    if (t == 0) {
        score[rowBase + g]          = p00;
        score[rowBase + g + 8]      = p01;
        score[rowBase + 16 + g]     = p10;
        score[rowBase + 16 + g + 8] = p11;
    }
    __syncthreads();

    // ---- 2-way softmax + store. out shape (B, 2, T)
    if (tid < PAIRS_PER_CTA) {
        float s1 = score[tid];
        float s2 = score[PAIRS_PER_CTA + tid];
        float d  = s2 - s1;
        float a1 = 1.0f / (1.0f + __expf(d));
        float a2 = 1.0f / (1.0f + __expf(-d));
        int gp = pair0 + tid;
        int b  = gp >> 12;          // / T_
        int tt = gp & (T_ - 1);
        out[(size_t)b * (2 * T_) + tt]      = a1;
        out[(size_t)b * (2 * T_) + T_ + tt] = a2;
    }
}

extern "C" void kernel_launch(void* const* d_in, const int* in_sizes, int n_in,
                              void* d_out, int out_size) {
    const float* h1   = (const float*)d_in[0];
    const float* h2   = (const float*)d_in[1];
    const float* w_tp = (const float*)d_in[2];
    const float* v_tp = (const float*)d_in[3];
    float* out = (float*)d_out;

    cudaFuncSetAttribute(topo_attn_kernel,
                         cudaFuncAttributeMaxDynamicSharedMemorySize, SMEM_BYTES);

    int grid = (B_ * T_) / PAIRS_PER_CTA;   // 1024
    topo_attn_kernel<<<grid, NTHREADS, SMEM_BYTES>>>(h1, h2, w_tp, v_tp, out);
}